// round 1
// baseline (speedup 1.0000x reference)
#include <cuda_runtime.h>
#include <math.h>

// Problem constants
#define Tn   3
#define Bn   16384
#define Dn   256
#define Hn   8
#define DHn  32
#define NLn  2
#define FFn  1024
#define NG   (Tn*Bn)        // 49152 row-groups
#define MROWS (NG*3)        // 147456 total rows
#define SCALE_F 0.17677669529663687f   // 1/sqrt(32)

// ---------------- device scratch (allocation-free) ----------------
__device__ float g_x[MROWS*Dn];   // residual stream
__device__ float g_h[MROWS*Dn];   // LN output / scratch
__device__ float g_q[MROWS*Dn];
__device__ float g_k[MROWS*Dn];
__device__ float g_v[MROWS*Dn];
__device__ float g_o[MROWS*Dn];   // attention output
__device__ float g_f[MROWS*FFn];  // FFN intermediate

// ---------------- build x from message passing ----------------
// x row r = n*3+s, n = t*B+b
// t=0: [term1-pred0, term2-pred2, term0]
// t=1: [term0+pred0, term2-pred1, term1]
// t=2: [term1+pred1, term0+pred2, term2]
__global__ void build_x_kernel(const float* __restrict__ term,
                               const float* __restrict__ pred,
                               float* __restrict__ x) {
    int idx4 = blockIdx.x * blockDim.x + threadIdx.x;    // float4 index
    const int nv = MROWS * (Dn/4);
    if (idx4 >= nv) return;
    int r  = idx4 / (Dn/4);
    int d4 = idx4 % (Dn/4);
    int s = r % 3;
    int n = r / 3;
    int t = n / Bn;
    int b = n % Bn;

    const int srcT[3][3] = {{1,2,0},{0,2,1},{1,0,2}};
    const int srcP[3][3] = {{0,2,-1},{0,1,-1},{1,2,-1}};
    const float sgn[3][3] = {{-1.f,-1.f,0.f},{1.f,-1.f,0.f},{1.f,1.f,0.f}};

    int tt = srcT[t][s];
    int pp = srcP[t][s];
    float sg = sgn[t][s];

    size_t toff = ((size_t)tt*Bn + b)*Dn + d4*4;
    float4 tv = *(const float4*)(term + toff);
    float4 res = tv;
    if (pp >= 0) {
        size_t poff = ((size_t)pp*Bn + b)*Dn + d4*4;
        float4 pv = *(const float4*)(pred + poff);
        res.x += sg*pv.x; res.y += sg*pv.y; res.z += sg*pv.z; res.w += sg*pv.w;
    }
    *(float4*)(x + (size_t)r*Dn + d4*4) = res;
}

// ---------------- layernorm: one warp per row of 256 ----------------
__global__ void ln_kernel(const float* __restrict__ x,
                          const float* __restrict__ gam,
                          const float* __restrict__ bet,
                          float* __restrict__ out) {
    int warp = (blockIdx.x * blockDim.x + threadIdx.x) >> 5;
    int lane = threadIdx.x & 31;
    if (warp >= MROWS) return;
    const float* row = x + (size_t)warp * Dn;
    float4 a0 = *(const float4*)(row + lane*8);
    float4 a1 = *(const float4*)(row + lane*8 + 4);
    float vals[8] = {a0.x,a0.y,a0.z,a0.w,a1.x,a1.y,a1.z,a1.w};
    float s = 0.f, sq = 0.f;
    #pragma unroll
    for (int i = 0; i < 8; i++) { s += vals[i]; sq += vals[i]*vals[i]; }
    #pragma unroll
    for (int o = 16; o > 0; o >>= 1) {
        s  += __shfl_xor_sync(0xffffffffu, s,  o);
        sq += __shfl_xor_sync(0xffffffffu, sq, o);
    }
    float mean = s * (1.0f/Dn);
    float var  = sq * (1.0f/Dn) - mean*mean;
    float rstd = rsqrtf(var + 1e-5f);
    float4 g0 = *(const float4*)(gam + lane*8);
    float4 g1 = *(const float4*)(gam + lane*8 + 4);
    float4 b0 = *(const float4*)(bet + lane*8);
    float4 b1 = *(const float4*)(bet + lane*8 + 4);
    float gs[8] = {g0.x,g0.y,g0.z,g0.w,g1.x,g1.y,g1.z,g1.w};
    float bs[8] = {b0.x,b0.y,b0.z,b0.w,b1.x,b1.y,b1.z,b1.w};
    float ov[8];
    #pragma unroll
    for (int i = 0; i < 8; i++)
        ov[i] = (vals[i]-mean)*rstd*gs[i] + bs[i];
    float* orow = out + (size_t)warp * Dn;
    *(float4*)(orow + lane*8)     = make_float4(ov[0],ov[1],ov[2],ov[3]);
    *(float4*)(orow + lane*8 + 4) = make_float4(ov[4],ov[5],ov[6],ov[7]);
}

// ---------------- SGEMM: C = act(A[M,K] @ W[K,N] + bias [+ resid]) ----------------
#define BM 128
#define BN 128
#define BK 8
#define TM 8
#define TN 8
// 256 threads

template<int ACT, bool RESID>
__global__ __launch_bounds__(256)
void gemm_kernel(const float* __restrict__ A, const float* __restrict__ W,
                 const float* __restrict__ bias, const float* __restrict__ resid,
                 float* __restrict__ C, int M, int K, int N) {
    __shared__ float As[BK][BM];
    __shared__ float Bs[BK][BN];
    int bm = blockIdx.y, bn = blockIdx.x;
    int tid = threadIdx.x;
    int tr = tid / (BN/TN);   // 0..15
    int tc = tid % (BN/TN);   // 0..15
    float acc[TM][TN];
    #pragma unroll
    for (int i=0;i<TM;i++)
        #pragma unroll
        for (int j=0;j<TN;j++) acc[i][j] = 0.f;

    int arow = tid >> 1, acol = (tid & 1) * 4;   // A tile: 128 x 8
    int wrow = tid >> 5, wcol = (tid & 31) * 4;  // W tile: 8 x 128

    const float* Ab = A + (size_t)(bm*BM) * K;
    const float* Wb = W + (size_t)(bn*BN);

    for (int k0 = 0; k0 < K; k0 += BK) {
        float4 av = *(const float4*)(Ab + (size_t)arow*K + k0 + acol);
        As[acol+0][arow] = av.x;
        As[acol+1][arow] = av.y;
        As[acol+2][arow] = av.z;
        As[acol+3][arow] = av.w;
        float4 wv = *(const float4*)(Wb + (size_t)(k0+wrow)*N + wcol);
        *(float4*)&Bs[wrow][wcol] = wv;
        __syncthreads();
        #pragma unroll
        for (int k = 0; k < BK; k++) {
            float ra[TM], rb[TN];
            #pragma unroll
            for (int i=0;i<TM;i++) ra[i] = As[k][tr*TM+i];
            #pragma unroll
            for (int j=0;j<TN;j++) rb[j] = Bs[k][tc*TN+j];
            #pragma unroll
            for (int i=0;i<TM;i++)
                #pragma unroll
                for (int j=0;j<TN;j++)
                    acc[i][j] += ra[i]*rb[j];
        }
        __syncthreads();
    }

    #pragma unroll
    for (int i=0;i<TM;i++) {
        int r = bm*BM + tr*TM + i;
        #pragma unroll
        for (int j=0;j<TN;j++) {
            int c = bn*BN + tc*TN + j;
            float vv = acc[i][j] + bias[c];
            if (RESID) vv += resid[(size_t)r*N + c];
            if (ACT == 1) vv = fmaxf(vv, 0.f);
            C[(size_t)r*N + c] = vv;
        }
    }
}

// ---------------- attention: 1 warp per (n, head) ----------------
__global__ void attn_kernel(const float* __restrict__ q,
                            const float* __restrict__ k,
                            const float* __restrict__ v,
                            float* __restrict__ o) {
    int widx = (blockIdx.x * blockDim.x + threadIdx.x) >> 5;
    int lane = threadIdx.x & 31;
    if (widx >= NG * Hn) return;
    int n = widx >> 3;
    int h = widx & 7;
    size_t base = (size_t)n*3*Dn + h*DHn + lane;
    float qs[3], ks[3], vs[3];
    #pragma unroll
    for (int s = 0; s < 3; s++) {
        qs[s] = q[base + s*Dn];
        ks[s] = k[base + s*Dn];
        vs[s] = v[base + s*Dn];
    }
    float sc[3][3];
    #pragma unroll
    for (int s = 0; s < 3; s++)
        #pragma unroll
        for (int t = 0; t < 3; t++) {
            float p = qs[s]*ks[t];
            #pragma unroll
            for (int off = 16; off > 0; off >>= 1)
                p += __shfl_xor_sync(0xffffffffu, p, off);
            sc[s][t] = p * SCALE_F;
        }
    #pragma unroll
    for (int s = 0; s < 3; s++) {
        float m = fmaxf(sc[s][0], fmaxf(sc[s][1], sc[s][2]));
        float e0 = __expf(sc[s][0]-m);
        float e1 = __expf(sc[s][1]-m);
        float e2 = __expf(sc[s][2]-m);
        float inv = 1.0f/(e0+e1+e2);
        float os = (e0*vs[0] + e1*vs[1] + e2*vs[2]) * inv;
        o[base + s*Dn] = os;
    }
}

// ---------------- mean over seq=3, write final output ----------------
__global__ void mean_kernel(const float* __restrict__ h, float* __restrict__ out) {
    int i = blockIdx.x * blockDim.x + threadIdx.x;   // float4 over NG*Dn
    const int nv = NG * (Dn/4);
    if (i >= nv) return;
    int n  = i / (Dn/4);
    int d4 = i % (Dn/4);
    size_t b0 = (size_t)(n*3)*Dn + d4*4;
    float4 a = *(const float4*)(h + b0);
    float4 b = *(const float4*)(h + b0 + Dn);
    float4 c = *(const float4*)(h + b0 + 2*Dn);
    const float inv3 = (1.0f/3.0f);
    float4 r;
    r.x = (a.x+b.x+c.x)*inv3;
    r.y = (a.y+b.y+c.y)*inv3;
    r.z = (a.z+b.z+c.z)*inv3;
    r.w = (a.w+b.w+c.w)*inv3;
    *(float4*)(out + (size_t)i*4) = r;
}

// ---------------- host ----------------
extern "C" void kernel_launch(void* const* d_in, const int* in_sizes, int n_in,
                              void* d_out, int out_size) {
    const float* term  = (const float*)d_in[0];
    const float* pred  = (const float*)d_in[1];
    const float* Wq    = (const float*)d_in[2];
    const float* Wk    = (const float*)d_in[3];
    const float* Wv    = (const float*)d_in[4];
    const float* Wo    = (const float*)d_in[5];
    const float* bq    = (const float*)d_in[6];
    const float* bk    = (const float*)d_in[7];
    const float* bv    = (const float*)d_in[8];
    const float* bo    = (const float*)d_in[9];
    const float* ln1g  = (const float*)d_in[10];
    const float* ln1b  = (const float*)d_in[11];
    const float* ln2g  = (const float*)d_in[12];
    const float* ln2b  = (const float*)d_in[13];
    const float* W1    = (const float*)d_in[14];
    const float* b1    = (const float*)d_in[15];
    const float* W2    = (const float*)d_in[16];
    const float* b2    = (const float*)d_in[17];
    const float* lnfg  = (const float*)d_in[18];
    const float* lnfb  = (const float*)d_in[19];
    float* out = (float*)d_out;

    float *x, *h, *q, *k, *v, *o, *f;
    cudaGetSymbolAddress((void**)&x, g_x);
    cudaGetSymbolAddress((void**)&h, g_h);
    cudaGetSymbolAddress((void**)&q, g_q);
    cudaGetSymbolAddress((void**)&k, g_k);
    cudaGetSymbolAddress((void**)&v, g_v);
    cudaGetSymbolAddress((void**)&o, g_o);
    cudaGetSymbolAddress((void**)&f, g_f);

    // build x
    {
        int nv = MROWS * (Dn/4);
        build_x_kernel<<<(nv + 255)/256, 256>>>(term, pred, x);
    }

    dim3 gD(Dn/BN,  MROWS/BM);   // N=256 GEMMs
    dim3 gF(FFn/BN, MROWS/BM);   // N=1024 GEMM

    for (int l = 0; l < NLn; l++) {
        const float* wq = Wq + (size_t)l*Dn*Dn;
        const float* wk = Wk + (size_t)l*Dn*Dn;
        const float* wv = Wv + (size_t)l*Dn*Dn;
        const float* wo = Wo + (size_t)l*Dn*Dn;
        const float* w1 = W1 + (size_t)l*Dn*FFn;
        const float* w2 = W2 + (size_t)l*FFn*Dn;
        const float* bql = bq + l*Dn;
        const float* bkl = bk + l*Dn;
        const float* bvl = bv + l*Dn;
        const float* bol = bo + l*Dn;
        const float* b1l = b1 + l*FFn;
        const float* b2l = b2 + l*Dn;

        // LN1
        ln_kernel<<<MROWS/8, 256>>>(x, ln1g + l*Dn, ln1b + l*Dn, h);
        // Q, K, V
        gemm_kernel<0,false><<<gD, 256>>>(h, wq, bql, nullptr, q, MROWS, Dn, Dn);
        gemm_kernel<0,false><<<gD, 256>>>(h, wk, bkl, nullptr, k, MROWS, Dn, Dn);
        gemm_kernel<0,false><<<gD, 256>>>(h, wv, bvl, nullptr, v, MROWS, Dn, Dn);
        // attention
        attn_kernel<<<NG*Hn/8, 256>>>(q, k, v, o);
        // output projection + residual
        gemm_kernel<0,true><<<gD, 256>>>(o, wo, bol, x, x, MROWS, Dn, Dn);
        // LN2
        ln_kernel<<<MROWS/8, 256>>>(x, ln2g + l*Dn, ln2b + l*Dn, h);
        // FFN
        gemm_kernel<1,false><<<gF, 256>>>(h, w1, b1l, nullptr, f, MROWS, Dn, FFn);
        gemm_kernel<0,true><<<gD, 256>>>(f, w2, b2l, x, x, MROWS, FFn, Dn);
    }

    // final LN + mean pool
    ln_kernel<<<MROWS/8, 256>>>(x, lnfg, lnfb, h);
    {
        int nv = NG * (Dn/4);
        mean_kernel<<<(nv + 255)/256, 256>>>(h, out);
    }
    (void)in_sizes; (void)n_in; (void)out_size;
}

// round 3
// speedup vs baseline: 3.4006x; 3.4006x over previous
#include <cuda_runtime.h>
#include <cstdint>
#include <math.h>

// Problem constants
#define Tn   3
#define Bn   16384
#define Dn   256
#define Hn   8
#define DHn  32
#define NLn  2
#define FFn  1024
#define NG   (Tn*Bn)        // 49152 row-groups
#define MROWS (NG*3)        // 147456 total rows
#define SCALE_F 0.17677669529663687f   // 1/sqrt(32)

// ---------------- device scratch (allocation-free) ----------------
__device__ float g_x[MROWS*Dn];       // residual stream
__device__ float g_h[MROWS*Dn];       // LN output (tf32-rounded)
__device__ float g_qkv[(size_t)MROWS*3*Dn];   // fused QKV output
__device__ float g_o[MROWS*Dn];       // attention output (tf32-rounded)
__device__ float g_f[(size_t)MROWS*FFn]; // FFN intermediate (tf32-rounded)
__device__ float g_wt[FFn*Dn];        // transposed weight scratch (max 1024x256)
__device__ float g_bqkv[3*Dn];        // concatenated qkv bias

// =================== helpers ===================
__device__ __forceinline__ uint32_t smem_u32(const void* p) {
    uint32_t a;
    asm("{ .reg .u64 t; cvta.to.shared.u64 t, %1; cvt.u32.u64 %0, t; }" : "=r"(a) : "l"(p));
    return a;
}
__device__ __forceinline__ float rtf32(float x) {
    float r; asm("cvt.rna.tf32.f32 %0, %1;" : "=f"(r) : "f"(x)); return r;
}
#define CP_ASYNC16(dst, src) \
    asm volatile("cp.async.cg.shared.global [%0], [%1], 16;" :: "r"(dst), "l"(src) : "memory")
#define CP_COMMIT() asm volatile("cp.async.commit_group;" ::: "memory")
#define CP_WAIT0()  asm volatile("cp.async.wait_group 0;" ::: "memory")

// mma.sync m16n8k8 tf32: D += A*B  (A row-major 16x8, B col-major 8x8, fp32 acc)
__device__ __forceinline__ void mma_tf32(float* c, const uint32_t* a, const uint32_t* b) {
    asm volatile(
        "mma.sync.aligned.m16n8k8.row.col.f32.tf32.tf32.f32 "
        "{%0,%1,%2,%3}, {%4,%5,%6,%7}, {%8,%9}, {%0,%1,%2,%3};"
        : "+f"(c[0]), "+f"(c[1]), "+f"(c[2]), "+f"(c[3])
        : "r"(a[0]), "r"(a[1]), "r"(a[2]), "r"(a[3]), "r"(b[0]), "r"(b[1]));
}

// ============ tensor-core GEMM: C = act(A[M,K] @ Bt[N,K]^T + bias [+resid]) ============
// grid = (N/128, M/128), block = 128 (4 warps, each 64x64 warp tile).
// Smem: 2 stages x (A 128x32 + B 128x32), rows padded to 36 floats (conflict-free).
#define LDSP 36
static constexpr int TILE_FLOATS  = 128 * LDSP;          // 4608
static constexpr int STAGE_FLOATS = 2 * TILE_FLOATS;     // A + B
static constexpr int GEMM_SMEM_BYTES = 2 * STAGE_FLOATS * 4;  // 73728

template<int ACT, bool RESID>
__global__ __launch_bounds__(128, 2)
void gemm_tc(const float* __restrict__ A, int lda,
             const float* __restrict__ Bt,          // [N,K] row-major (pre-transposed)
             const float* __restrict__ bias,
             const float* __restrict__ resid,
             float* __restrict__ C, int ldc, int K) {
    extern __shared__ float smem[];
    const int tid = threadIdx.x;
    const int wid = tid >> 5, lane = tid & 31;
    const int wr = wid >> 1, wc = wid & 1;      // 2x2 warp grid
    const int gr = lane >> 2, gc = lane & 3;
    const int bm = blockIdx.y, bn = blockIdx.x;

    const float* Ag0 = A  + (size_t)bm * 128 * lda;
    const float* Bg0 = Bt + (size_t)bn * 128 * K;
    const int NC = K >> 5;

    float acc[4][8][4];
    #pragma unroll
    for (int mt = 0; mt < 4; mt++)
        #pragma unroll
        for (int nt = 0; nt < 8; nt++)
            #pragma unroll
            for (int i = 0; i < 4; i++) acc[mt][nt][i] = 0.f;

    const int lrow = tid >> 3;          // base row for loads (row .. +112 step 16)
    const int lc4  = tid & 7;           // 16B column slot

    auto load_chunk = [&](int kc, int s) {
        float* As = smem + s * STAGE_FLOATS;
        float* Bs = As + TILE_FLOATS;
        const float* Agc = Ag0 + kc * 32;
        const float* Bgc = Bg0 + kc * 32;
        #pragma unroll
        for (int j = 0; j < 8; j++) {
            int row = lrow + j * 16;
            uint32_t da = smem_u32(As + row * LDSP + lc4 * 4);
            CP_ASYNC16(da, Agc + (size_t)row * lda + lc4 * 4);
            uint32_t db = smem_u32(Bs + row * LDSP + lc4 * 4);
            CP_ASYNC16(db, Bgc + (size_t)row * K + lc4 * 4);
        }
        CP_COMMIT();
    };

    load_chunk(0, 0);
    CP_WAIT0();
    __syncthreads();

    for (int i = 0; i < NC; i++) {
        int s = i & 1;
        if (i + 1 < NC) load_chunk(i + 1, s ^ 1);   // async prefetch
        const float* As = smem + s * STAGE_FLOATS;
        const float* Bs = As + TILE_FLOATS;
        #pragma unroll
        for (int kk = 0; kk < 4; kk++) {
            const int kc = kk * 8;
            uint32_t a[4][4], b[8][2];
            #pragma unroll
            for (int mt = 0; mt < 4; mt++) {
                const float* p = As + (wr*64 + mt*16 + gr) * LDSP + kc + gc;
                a[mt][0] = __float_as_uint(p[0]);
                a[mt][1] = __float_as_uint(p[8*LDSP]);
                a[mt][2] = __float_as_uint(p[4]);
                a[mt][3] = __float_as_uint(p[8*LDSP + 4]);
            }
            #pragma unroll
            for (int nt = 0; nt < 8; nt++) {
                const float* p = Bs + (wc*64 + nt*8 + gr) * LDSP + kc + gc;
                b[nt][0] = __float_as_uint(p[0]);
                b[nt][1] = __float_as_uint(p[4]);
            }
            #pragma unroll
            for (int mt = 0; mt < 4; mt++)
                #pragma unroll
                for (int nt = 0; nt < 8; nt++)
                    mma_tf32(acc[mt][nt], a[mt], b[nt]);
        }
        CP_WAIT0();       // prefetched chunk landed
        __syncthreads();
    }

    // ---- epilogue ----
    const int cbase = bn * 128 + wc * 64;
    #pragma unroll
    for (int mt = 0; mt < 4; mt++) {
        #pragma unroll
        for (int rr = 0; rr < 2; rr++) {
            int r = bm * 128 + wr * 64 + mt * 16 + gr + rr * 8;
            float* crow = C + (size_t)r * ldc + cbase;
            const float* rrow = RESID ? (resid + (size_t)r * ldc + cbase) : nullptr;
            #pragma unroll
            for (int nt = 0; nt < 8; nt++) {
                int ci = nt * 8 + 2 * gc;
                float v0 = acc[mt][nt][rr*2 + 0] + bias[cbase + ci];
                float v1 = acc[mt][nt][rr*2 + 1] + bias[cbase + ci + 1];
                if (RESID) {
                    float2 rv = *(const float2*)(rrow + ci);
                    v0 += rv.x; v1 += rv.y;
                }
                if (ACT == 1) {
                    v0 = rtf32(fmaxf(v0, 0.f));
                    v1 = rtf32(fmaxf(v1, 0.f));
                }
                *(float2*)(crow + ci) = make_float2(v0, v1);
            }
        }
    }
}

// ---------------- build x from message passing ----------------
__global__ void build_x_kernel(const float* __restrict__ term,
                               const float* __restrict__ pred,
                               float* __restrict__ x) {
    int idx4 = blockIdx.x * blockDim.x + threadIdx.x;
    const int nv = MROWS * (Dn/4);
    if (idx4 >= nv) return;
    int r  = idx4 / (Dn/4);
    int d4 = idx4 % (Dn/4);
    int s = r % 3;
    int n = r / 3;
    int t = n / Bn;
    int b = n % Bn;
    const int srcT[3][3] = {{1,2,0},{0,2,1},{1,0,2}};
    const int srcP[3][3] = {{0,2,-1},{0,1,-1},{1,2,-1}};
    const float sgn[3][3] = {{-1.f,-1.f,0.f},{1.f,-1.f,0.f},{1.f,1.f,0.f}};
    int tt = srcT[t][s];
    int pp = srcP[t][s];
    float sg = sgn[t][s];
    size_t toff = ((size_t)tt*Bn + b)*Dn + d4*4;
    float4 tv = *(const float4*)(term + toff);
    float4 res = tv;
    if (pp >= 0) {
        size_t poff = ((size_t)pp*Bn + b)*Dn + d4*4;
        float4 pv = *(const float4*)(pred + poff);
        res.x += sg*pv.x; res.y += sg*pv.y; res.z += sg*pv.z; res.w += sg*pv.w;
    }
    *(float4*)(x + (size_t)r*Dn + d4*4) = res;
}

// ---------------- layernorm: one warp per row of 256 ----------------
__global__ void ln_kernel(const float* __restrict__ x,
                          const float* __restrict__ gam,
                          const float* __restrict__ bet,
                          float* __restrict__ out, int rnd) {
    int warp = (blockIdx.x * blockDim.x + threadIdx.x) >> 5;
    int lane = threadIdx.x & 31;
    if (warp >= MROWS) return;
    const float* row = x + (size_t)warp * Dn;
    float4 a0 = *(const float4*)(row + lane*8);
    float4 a1 = *(const float4*)(row + lane*8 + 4);
    float vals[8] = {a0.x,a0.y,a0.z,a0.w,a1.x,a1.y,a1.z,a1.w};
    float s = 0.f, sq = 0.f;
    #pragma unroll
    for (int i = 0; i < 8; i++) { s += vals[i]; sq += vals[i]*vals[i]; }
    #pragma unroll
    for (int o = 16; o > 0; o >>= 1) {
        s  += __shfl_xor_sync(0xffffffffu, s,  o);
        sq += __shfl_xor_sync(0xffffffffu, sq, o);
    }
    float mean = s * (1.0f/Dn);
    float var  = sq * (1.0f/Dn) - mean*mean;
    float rstd = rsqrtf(var + 1e-5f);
    float4 g0 = *(const float4*)(gam + lane*8);
    float4 g1 = *(const float4*)(gam + lane*8 + 4);
    float4 b0 = *(const float4*)(bet + lane*8);
    float4 b1 = *(const float4*)(bet + lane*8 + 4);
    float gs[8] = {g0.x,g0.y,g0.z,g0.w,g1.x,g1.y,g1.z,g1.w};
    float bs[8] = {b0.x,b0.y,b0.z,b0.w,b1.x,b1.y,b1.z,b1.w};
    float ov[8];
    #pragma unroll
    for (int i = 0; i < 8; i++) {
        ov[i] = (vals[i]-mean)*rstd*gs[i] + bs[i];
        if (rnd) ov[i] = rtf32(ov[i]);
    }
    float* orow = out + (size_t)warp * Dn;
    *(float4*)(orow + lane*8)     = make_float4(ov[0],ov[1],ov[2],ov[3]);
    *(float4*)(orow + lane*8 + 4) = make_float4(ov[4],ov[5],ov[6],ov[7]);
}

// ---------------- attention on fused qkv buffer: 1 warp per (n, head) ----------------
__global__ void attn_kernel(const float* __restrict__ qkv, float* __restrict__ o) {
    int widx = (blockIdx.x * blockDim.x + threadIdx.x) >> 5;
    int lane = threadIdx.x & 31;
    if (widx >= NG * Hn) return;
    int n = widx >> 3;
    int h = widx & 7;
    size_t rb = (size_t)n * 3 * (3*Dn) + h*DHn + lane;
    float qs[3], ks[3], vs[3];
    #pragma unroll
    for (int s = 0; s < 3; s++) {
        qs[s] = qkv[rb + (size_t)s*(3*Dn)];
        ks[s] = qkv[rb + (size_t)s*(3*Dn) + Dn];
        vs[s] = qkv[rb + (size_t)s*(3*Dn) + 2*Dn];
    }
    float sc[3][3];
    #pragma unroll
    for (int s = 0; s < 3; s++)
        #pragma unroll
        for (int t = 0; t < 3; t++) {
            float p = qs[s]*ks[t];
            #pragma unroll
            for (int off = 16; off > 0; off >>= 1)
                p += __shfl_xor_sync(0xffffffffu, p, off);
            sc[s][t] = p * SCALE_F;
        }
    #pragma unroll
    for (int s = 0; s < 3; s++) {
        float m = fmaxf(sc[s][0], fmaxf(sc[s][1], sc[s][2]));
        float e0 = __expf(sc[s][0]-m);
        float e1 = __expf(sc[s][1]-m);
        float e2 = __expf(sc[s][2]-m);
        float inv = 1.0f/(e0+e1+e2);
        float os = (e0*vs[0] + e1*vs[1] + e2*vs[2]) * inv;
        o[(size_t)(n*3+s)*Dn + h*DHn + lane] = rtf32(os);
    }
}

// ---------------- weight transpose [K,N] -> [N,K] with tf32 rounding ----------------
__global__ void transpose_rt(const float* __restrict__ in, float* __restrict__ out,
                             int K, int N) {
    __shared__ float t[32][33];
    int n0 = blockIdx.x*32, k0 = blockIdx.y*32;
    int tx = threadIdx.x, ty = threadIdx.y;   // 32x8
    #pragma unroll
    for (int i = ty; i < 32; i += 8)
        t[i][tx] = in[(size_t)(k0+i)*N + n0+tx];
    __syncthreads();
    #pragma unroll
    for (int i = ty; i < 32; i += 8)
        out[(size_t)(n0+i)*K + k0+tx] = rtf32(t[tx][i]);
}

__global__ void concat_bias_kernel(const float* __restrict__ bq, const float* __restrict__ bk,
                                   const float* __restrict__ bv, float* __restrict__ out) {
    int i = blockIdx.x*blockDim.x + threadIdx.x;
    if (i >= 3*Dn) return;
    if (i < Dn)        out[i] = bq[i];
    else if (i < 2*Dn) out[i] = bk[i-Dn];
    else               out[i] = bv[i-2*Dn];
}

// ---------------- mean over seq=3, write final output ----------------
__global__ void mean_kernel(const float* __restrict__ h, float* __restrict__ out) {
    int i = blockIdx.x * blockDim.x + threadIdx.x;
    const int nv = NG * (Dn/4);
    if (i >= nv) return;
    int n  = i / (Dn/4);
    int d4 = i % (Dn/4);
    size_t b0 = (size_t)(n*3)*Dn + d4*4;
    float4 a = *(const float4*)(h + b0);
    float4 b = *(const float4*)(h + b0 + Dn);
    float4 c = *(const float4*)(h + b0 + 2*Dn);
    const float inv3 = (1.0f/3.0f);
    float4 r;
    r.x = (a.x+b.x+c.x)*inv3;
    r.y = (a.y+b.y+c.y)*inv3;
    r.z = (a.z+b.z+c.z)*inv3;
    r.w = (a.w+b.w+c.w)*inv3;
    *(float4*)(out + (size_t)i*4) = r;
}

// ---------------- host ----------------
extern "C" void kernel_launch(void* const* d_in, const int* in_sizes, int n_in,
                              void* d_out, int out_size) {
    const float* term  = (const float*)d_in[0];
    const float* pred  = (const float*)d_in[1];
    const float* Wq    = (const float*)d_in[2];
    const float* Wk    = (const float*)d_in[3];
    const float* Wv    = (const float*)d_in[4];
    const float* Wo    = (const float*)d_in[5];
    const float* bq    = (const float*)d_in[6];
    const float* bk    = (const float*)d_in[7];
    const float* bv    = (const float*)d_in[8];
    const float* bo    = (const float*)d_in[9];
    const float* ln1g  = (const float*)d_in[10];
    const float* ln1b  = (const float*)d_in[11];
    const float* ln2g  = (const float*)d_in[12];
    const float* ln2b  = (const float*)d_in[13];
    const float* W1    = (const float*)d_in[14];
    const float* b1    = (const float*)d_in[15];
    const float* W2    = (const float*)d_in[16];
    const float* b2    = (const float*)d_in[17];
    const float* lnfg  = (const float*)d_in[18];
    const float* lnfb  = (const float*)d_in[19];
    float* out = (float*)d_out;

    float *x, *h, *qkv, *o, *f, *wt, *bqkv;
    cudaGetSymbolAddress((void**)&x,   g_x);
    cudaGetSymbolAddress((void**)&h,   g_h);
    cudaGetSymbolAddress((void**)&qkv, g_qkv);
    cudaGetSymbolAddress((void**)&o,   g_o);
    cudaGetSymbolAddress((void**)&f,   g_f);
    cudaGetSymbolAddress((void**)&wt,  g_wt);
    cudaGetSymbolAddress((void**)&bqkv,g_bqkv);

    cudaFuncSetAttribute(gemm_tc<0,false>, cudaFuncAttributeMaxDynamicSharedMemorySize, GEMM_SMEM_BYTES);
    cudaFuncSetAttribute(gemm_tc<0,true >, cudaFuncAttributeMaxDynamicSharedMemorySize, GEMM_SMEM_BYTES);
    cudaFuncSetAttribute(gemm_tc<1,false>, cudaFuncAttributeMaxDynamicSharedMemorySize, GEMM_SMEM_BYTES);

    // build x
    {
        int nv = MROWS * (Dn/4);
        build_x_kernel<<<(nv + 255)/256, 256>>>(term, pred, x);
    }

    dim3 tblk(32, 8);
    for (int l = 0; l < NLn; l++) {
        const float* wq = Wq + (size_t)l*Dn*Dn;
        const float* wk = Wk + (size_t)l*Dn*Dn;
        const float* wv = Wv + (size_t)l*Dn*Dn;
        const float* wo = Wo + (size_t)l*Dn*Dn;
        const float* w1 = W1 + (size_t)l*Dn*FFn;
        const float* w2 = W2 + (size_t)l*FFn*Dn;

        // LN1 (tf32-rounded output -> MMA input)
        ln_kernel<<<MROWS/8, 256>>>(x, ln1g + l*Dn, ln1b + l*Dn, h, 1);

        // fused QKV: transpose Wq/Wk/Wv -> wt rows [0:768)
        transpose_rt<<<dim3(8,8), tblk>>>(wq, wt,            Dn, Dn);
        transpose_rt<<<dim3(8,8), tblk>>>(wk, wt + Dn*Dn,    Dn, Dn);
        transpose_rt<<<dim3(8,8), tblk>>>(wv, wt + 2*Dn*Dn,  Dn, Dn);
        concat_bias_kernel<<<3, 256>>>(bq + l*Dn, bk + l*Dn, bv + l*Dn, bqkv);
        gemm_tc<0,false><<<dim3(6, MROWS/128), 128, GEMM_SMEM_BYTES>>>(
            h, Dn, wt, bqkv, nullptr, qkv, 3*Dn, Dn);

        // attention
        attn_kernel<<<NG*Hn/8, 256>>>(qkv, o);

        // output projection + residual
        transpose_rt<<<dim3(8,8), tblk>>>(wo, wt, Dn, Dn);
        gemm_tc<0,true><<<dim3(2, MROWS/128), 128, GEMM_SMEM_BYTES>>>(
            o, Dn, wt, bo + l*Dn, x, x, Dn, Dn);

        // LN2
        ln_kernel<<<MROWS/8, 256>>>(x, ln2g + l*Dn, ln2b + l*Dn, h, 1);

        // FFN up (relu + tf32-round fused)
        transpose_rt<<<dim3(32,8), tblk>>>(w1, wt, Dn, FFn);
        gemm_tc<1,false><<<dim3(8, MROWS/128), 128, GEMM_SMEM_BYTES>>>(
            h, Dn, wt, b1 + l*FFn, nullptr, f, FFn, Dn);

        // FFN down + residual
        transpose_rt<<<dim3(8,32), tblk>>>(w2, wt, FFn, Dn);
        gemm_tc<0,true><<<dim3(2, MROWS/128), 128, GEMM_SMEM_BYTES>>>(
            f, FFn, wt, b2 + l*Dn, x, x, Dn, FFn);
    }

    // final LN (full fp32, no rounding) + mean pool
    ln_kernel<<<MROWS/8, 256>>>(x, lnfg, lnfb, h, 0);
    {
        int nv = NG * (Dn/4);
        mean_kernel<<<(nv + 255)/256, 256>>>(h, out);
    }
    (void)in_sizes; (void)n_in; (void)out_size;
}

// round 4
// speedup vs baseline: 3.6400x; 1.0704x over previous
#include <cuda_runtime.h>
#include <cuda_bf16.h>
#include <cstdint>
#include <math.h>

// Problem constants
#define Tn   3
#define Bn   16384
#define Dn   256
#define Hn   8
#define DHn  32
#define NLn  2
#define FFn  1024
#define NG   (Tn*Bn)        // 49152 row-groups
#define MROWS (NG*3)        // 147456 total rows
#define SCALE_F 0.17677669529663687f   // 1/sqrt(32)

typedef __nv_bfloat16 bf16;

// ---------------- device scratch (allocation-free) ----------------
__device__ float g_x[MROWS*Dn];                 // residual stream (fp32)
__device__ bf16  g_h[MROWS*Dn];                 // LN output (bf16)
__device__ bf16  g_qkv[(size_t)MROWS*3*Dn];     // fused QKV output (bf16)
__device__ bf16  g_o[MROWS*Dn];                 // attention output (bf16)
__device__ bf16  g_f[(size_t)MROWS*FFn];        // FFN intermediate (bf16)
// transposed bf16 weights, both layers:
// per-layer: qkvT[768x256] @0, woT[256x256] @196608, w1T[1024x256] @262144, w2T[256x1024] @524288
#define WT_LAYER 786432
__device__ bf16  g_wt[2*WT_LAYER];
__device__ float g_bqkv[2*3*Dn];                // concatenated qkv bias, both layers

// =================== helpers ===================
__device__ __forceinline__ uint32_t smem_u32(const void* p) {
    uint32_t a;
    asm("{ .reg .u64 t; cvta.to.shared.u64 t, %1; cvt.u32.u64 %0, t; }" : "=r"(a) : "l"(p));
    return a;
}
#define CP_ASYNC16(dst, src) \
    asm volatile("cp.async.cg.shared.global [%0], [%1], 16;" :: "r"(dst), "l"(src) : "memory")
#define CP_COMMIT() asm volatile("cp.async.commit_group;" ::: "memory")
#define CP_WAIT0()  asm volatile("cp.async.wait_group 0;" ::: "memory")

// mma.sync m16n8k16 bf16: D += A*B (A row-major 16x16, B col-major 16x8, fp32 acc)
__device__ __forceinline__ void mma_bf16(float* c, const uint32_t* a, const uint32_t* b) {
    asm volatile(
        "mma.sync.aligned.m16n8k16.row.col.f32.bf16.bf16.f32 "
        "{%0,%1,%2,%3}, {%4,%5,%6,%7}, {%8,%9}, {%0,%1,%2,%3};"
        : "+f"(c[0]), "+f"(c[1]), "+f"(c[2]), "+f"(c[3])
        : "r"(a[0]), "r"(a[1]), "r"(a[2]), "r"(a[3]), "r"(b[0]), "r"(b[1]));
}

// ============ bf16 tensor-core GEMM: C = act(A[M,K] @ Bt[N,K]^T + bias [+resid]) ============
// grid = (N/128, M/128), block = 128 (4 warps, each 64x64 warp tile).
// Smem: 2 stages x (A 128x64 + B 128x64) bf16, rows padded to 72 (conflict-free).
#define KC   64
#define LDSB 72
static constexpr int TILE_BF   = 128 * LDSB;            // bf16 elems per tile
static constexpr int STAGE_BF  = 2 * TILE_BF;           // A + B
static constexpr int GEMM_SMEM_BYTES = 2 * STAGE_BF * 2;  // 73728

template<int ACT, bool RESID, bool OBF>
__global__ __launch_bounds__(128, 2)
void gemm_tc(const bf16* __restrict__ A, int lda,
             const bf16* __restrict__ Bt,           // [N,K] row-major (pre-transposed)
             const float* __restrict__ bias,
             const float* __restrict__ resid,
             void* __restrict__ Cv, int ldc, int K) {
    extern __shared__ bf16 smem[];
    const int tid = threadIdx.x;
    const int wid = tid >> 5, lane = tid & 31;
    const int wr = wid >> 1, wc = wid & 1;      // 2x2 warp grid
    const int gr = lane >> 2, gc = lane & 3;
    const int bm = blockIdx.y, bn = blockIdx.x;

    const bf16* Ag0 = A  + (size_t)bm * 128 * lda;
    const bf16* Bg0 = Bt + (size_t)bn * 128 * K;
    const int NC = K / KC;

    float acc[4][8][4];
    #pragma unroll
    for (int mt = 0; mt < 4; mt++)
        #pragma unroll
        for (int nt = 0; nt < 8; nt++)
            #pragma unroll
            for (int i = 0; i < 4; i++) acc[mt][nt][i] = 0.f;

    auto load_chunk = [&](int kc, int s) {
        bf16* As = smem + s * STAGE_BF;
        bf16* Bs = As + TILE_BF;
        const bf16* Agc = Ag0 + kc * KC;
        const bf16* Bgc = Bg0 + kc * KC;
        #pragma unroll
        for (int j = 0; j < 8; j++) {
            int slot = tid + 128 * j;           // 1024 slots of 16B per tile
            int row  = slot >> 3;
            int c8   = slot & 7;                // 8-bf16 column slot
            uint32_t da = smem_u32(As + row * LDSB + c8 * 8);
            CP_ASYNC16(da, Agc + (size_t)row * lda + c8 * 8);
            uint32_t db = smem_u32(Bs + row * LDSB + c8 * 8);
            CP_ASYNC16(db, Bgc + (size_t)row * K + c8 * 8);
        }
        CP_COMMIT();
    };

    load_chunk(0, 0);
    CP_WAIT0();
    __syncthreads();

    for (int i = 0; i < NC; i++) {
        int s = i & 1;
        if (i + 1 < NC) load_chunk(i + 1, s ^ 1);   // async prefetch
        const bf16* As = smem + s * STAGE_BF;
        const bf16* Bs = As + TILE_BF;
        #pragma unroll
        for (int kk = 0; kk < 4; kk++) {            // 4 x k16 per 64-chunk
            const int kc0 = kk * 16;
            uint32_t a[4][4], b[8][2];
            #pragma unroll
            for (int mt = 0; mt < 4; mt++) {
                const bf16* p = As + (wr*64 + mt*16 + gr) * LDSB + kc0 + 2*gc;
                a[mt][0] = *(const uint32_t*)(p);
                a[mt][1] = *(const uint32_t*)(p + 8*LDSB);
                a[mt][2] = *(const uint32_t*)(p + 8);
                a[mt][3] = *(const uint32_t*)(p + 8*LDSB + 8);
            }
            #pragma unroll
            for (int nt = 0; nt < 8; nt++) {
                const bf16* p = Bs + (wc*64 + nt*8 + gr) * LDSB + kc0 + 2*gc;
                b[nt][0] = *(const uint32_t*)(p);
                b[nt][1] = *(const uint32_t*)(p + 8);
            }
            #pragma unroll
            for (int mt = 0; mt < 4; mt++)
                #pragma unroll
                for (int nt = 0; nt < 8; nt++)
                    mma_bf16(acc[mt][nt], a[mt], b[nt]);
        }
        CP_WAIT0();
        __syncthreads();
    }

    // ---- epilogue ----
    const int cbase = bn * 128 + wc * 64;
    #pragma unroll
    for (int mt = 0; mt < 4; mt++) {
        #pragma unroll
        for (int rr = 0; rr < 2; rr++) {
            int r = bm * 128 + wr * 64 + mt * 16 + gr + rr * 8;
            const float* rrow = RESID ? (resid + (size_t)r * ldc + cbase) : nullptr;
            #pragma unroll
            for (int nt = 0; nt < 8; nt++) {
                int ci = nt * 8 + 2 * gc;
                float v0 = acc[mt][nt][rr*2 + 0] + bias[cbase + ci];
                float v1 = acc[mt][nt][rr*2 + 1] + bias[cbase + ci + 1];
                if (RESID) {
                    float2 rv = *(const float2*)(rrow + ci);
                    v0 += rv.x; v1 += rv.y;
                }
                if (ACT == 1) { v0 = fmaxf(v0, 0.f); v1 = fmaxf(v1, 0.f); }
                if (OBF) {
                    bf16* crow = (bf16*)Cv + (size_t)r * ldc + cbase;
                    __nv_bfloat162 bv;
                    bv.x = __float2bfloat16_rn(v0);
                    bv.y = __float2bfloat16_rn(v1);
                    *(__nv_bfloat162*)(crow + ci) = bv;
                } else {
                    float* crow = (float*)Cv + (size_t)r * ldc + cbase;
                    *(float2*)(crow + ci) = make_float2(v0, v1);
                }
            }
        }
    }
}

// ---------------- build x from message passing ----------------
__global__ void build_x_kernel(const float* __restrict__ term,
                               const float* __restrict__ pred,
                               float* __restrict__ x) {
    int idx4 = blockIdx.x * blockDim.x + threadIdx.x;
    const int nv = MROWS * (Dn/4);
    if (idx4 >= nv) return;
    int r  = idx4 / (Dn/4);
    int d4 = idx4 % (Dn/4);
    int s = r % 3;
    int n = r / 3;
    int t = n / Bn;
    int b = n % Bn;
    const int srcT[3][3] = {{1,2,0},{0,2,1},{1,0,2}};
    const int srcP[3][3] = {{0,2,-1},{0,1,-1},{1,2,-1}};
    const float sgn[3][3] = {{-1.f,-1.f,0.f},{1.f,-1.f,0.f},{1.f,1.f,0.f}};
    int tt = srcT[t][s];
    int pp = srcP[t][s];
    float sg = sgn[t][s];
    size_t toff = ((size_t)tt*Bn + b)*Dn + d4*4;
    float4 tv = *(const float4*)(term + toff);
    float4 res = tv;
    if (pp >= 0) {
        size_t poff = ((size_t)pp*Bn + b)*Dn + d4*4;
        float4 pv = *(const float4*)(pred + poff);
        res.x += sg*pv.x; res.y += sg*pv.y; res.z += sg*pv.z; res.w += sg*pv.w;
    }
    *(float4*)(x + (size_t)r*Dn + d4*4) = res;
}

// ---------------- layernorm: one warp per row, bf16 output ----------------
__global__ void ln_kernel(const float* __restrict__ x,
                          const float* __restrict__ gam,
                          const float* __restrict__ bet,
                          bf16* __restrict__ out) {
    int warp = (blockIdx.x * blockDim.x + threadIdx.x) >> 5;
    int lane = threadIdx.x & 31;
    if (warp >= MROWS) return;
    const float* row = x + (size_t)warp * Dn;
    float4 a0 = *(const float4*)(row + lane*8);
    float4 a1 = *(const float4*)(row + lane*8 + 4);
    float vals[8] = {a0.x,a0.y,a0.z,a0.w,a1.x,a1.y,a1.z,a1.w};
    float s = 0.f, sq = 0.f;
    #pragma unroll
    for (int i = 0; i < 8; i++) { s += vals[i]; sq += vals[i]*vals[i]; }
    #pragma unroll
    for (int o = 16; o > 0; o >>= 1) {
        s  += __shfl_xor_sync(0xffffffffu, s,  o);
        sq += __shfl_xor_sync(0xffffffffu, sq, o);
    }
    float mean = s * (1.0f/Dn);
    float var  = sq * (1.0f/Dn) - mean*mean;
    float rstd = rsqrtf(var + 1e-5f);
    float4 g0 = *(const float4*)(gam + lane*8);
    float4 g1 = *(const float4*)(gam + lane*8 + 4);
    float4 b0 = *(const float4*)(bet + lane*8);
    float4 b1 = *(const float4*)(bet + lane*8 + 4);
    float gs[8] = {g0.x,g0.y,g0.z,g0.w,g1.x,g1.y,g1.z,g1.w};
    float bs[8] = {b0.x,b0.y,b0.z,b0.w,b1.x,b1.y,b1.z,b1.w};
    __nv_bfloat162 ov[4];
    #pragma unroll
    for (int i = 0; i < 4; i++) {
        float u0 = (vals[2*i]  -mean)*rstd*gs[2*i]   + bs[2*i];
        float u1 = (vals[2*i+1]-mean)*rstd*gs[2*i+1] + bs[2*i+1];
        ov[i].x = __float2bfloat16_rn(u0);
        ov[i].y = __float2bfloat16_rn(u1);
    }
    *(uint4*)(out + (size_t)warp * Dn + lane*8) = *(uint4*)ov;
}

// ---------------- attention on fused qkv buffer (bf16): 1 warp per (n, head) ----------------
__global__ void attn_kernel(const bf16* __restrict__ qkv, bf16* __restrict__ o) {
    int widx = (blockIdx.x * blockDim.x + threadIdx.x) >> 5;
    int lane = threadIdx.x & 31;
    if (widx >= NG * Hn) return;
    int n = widx >> 3;
    int h = widx & 7;
    size_t rb = (size_t)n * 3 * (3*Dn) + h*DHn + lane;
    float qs[3], ks[3], vs[3];
    #pragma unroll
    for (int s = 0; s < 3; s++) {
        qs[s] = __bfloat162float(qkv[rb + (size_t)s*(3*Dn)]);
        ks[s] = __bfloat162float(qkv[rb + (size_t)s*(3*Dn) + Dn]);
        vs[s] = __bfloat162float(qkv[rb + (size_t)s*(3*Dn) + 2*Dn]);
    }
    float sc[3][3];
    #pragma unroll
    for (int s = 0; s < 3; s++)
        #pragma unroll
        for (int t = 0; t < 3; t++) {
            float p = qs[s]*ks[t];
            #pragma unroll
            for (int off = 16; off > 0; off >>= 1)
                p += __shfl_xor_sync(0xffffffffu, p, off);
            sc[s][t] = p * SCALE_F;
        }
    #pragma unroll
    for (int s = 0; s < 3; s++) {
        float m = fmaxf(sc[s][0], fmaxf(sc[s][1], sc[s][2]));
        float e0 = __expf(sc[s][0]-m);
        float e1 = __expf(sc[s][1]-m);
        float e2 = __expf(sc[s][2]-m);
        float inv = 1.0f/(e0+e1+e2);
        float os = (e0*vs[0] + e1*vs[1] + e2*vs[2]) * inv;
        o[(size_t)(n*3+s)*Dn + h*DHn + lane] = __float2bfloat16_rn(os);
    }
}

// ---------------- one-shot transpose+convert of all weights (both layers) ----------------
// grid.x = 2*768 blocks of (32,8): per layer 768 tiles:
//   [0,192): qkvT tiles (wq/wk/wv 256x256 each), [192,256): wo, [256,512): w1, [512,768): w2
__global__ void transpose_all(const float* __restrict__ Wq, const float* __restrict__ Wk,
                              const float* __restrict__ Wv, const float* __restrict__ Wo,
                              const float* __restrict__ W1, const float* __restrict__ W2,
                              bf16* __restrict__ wt) {
    __shared__ float t[32][33];
    int bid = blockIdx.x;
    int l = bid / 768;
    int tt = bid % 768;
    const float* in; bf16* out; int K, N, n0, k0, outld;
    if (tt < 192) {
        int which = tt / 64; int q = tt % 64;
        const float* Ws[3] = {Wq, Wk, Wv};
        in = Ws[which] + (size_t)l*Dn*Dn;
        out = wt + (size_t)l*WT_LAYER + which*Dn*Dn;
        K = Dn; N = Dn; outld = Dn;
        n0 = (q & 7) * 32; k0 = (q >> 3) * 32;
    } else if (tt < 256) {
        int q = tt - 192;
        in = Wo + (size_t)l*Dn*Dn;
        out = wt + (size_t)l*WT_LAYER + 196608;
        K = Dn; N = Dn; outld = Dn;
        n0 = (q & 7) * 32; k0 = (q >> 3) * 32;
    } else if (tt < 512) {
        int q = tt - 256;
        in = W1 + (size_t)l*Dn*FFn;
        out = wt + (size_t)l*WT_LAYER + 262144;
        K = Dn; N = FFn; outld = Dn;
        n0 = (q & 31) * 32; k0 = (q >> 5) * 32;
    } else {
        int q = tt - 512;
        in = W2 + (size_t)l*FFn*Dn;
        out = wt + (size_t)l*WT_LAYER + 524288;
        K = FFn; N = Dn; outld = FFn;
        n0 = (q & 7) * 32; k0 = (q >> 3) * 32;
    }
    int tx = threadIdx.x, ty = threadIdx.y;   // 32 x 8
    #pragma unroll
    for (int i = ty; i < 32; i += 8)
        t[i][tx] = in[(size_t)(k0+i)*N + n0+tx];
    __syncthreads();
    #pragma unroll
    for (int i = ty; i < 32; i += 8)
        out[(size_t)(n0+i)*outld + k0+tx] = __float2bfloat16_rn(t[tx][i]);
}

__global__ void concat_bias_kernel(const float* __restrict__ bq, const float* __restrict__ bk,
                                   const float* __restrict__ bv, float* __restrict__ out) {
    int i = blockIdx.x*blockDim.x + threadIdx.x;   // 2*768
    if (i >= 2*3*Dn) return;
    int l = i / (3*Dn);
    int j = i % (3*Dn);
    float v;
    if (j < Dn)        v = bq[l*Dn + j];
    else if (j < 2*Dn) v = bk[l*Dn + j-Dn];
    else               v = bv[l*Dn + j-2*Dn];
    out[i] = v;
}

// ---------------- fused final LN + mean-pool: 1 warp per group ----------------
__global__ void ln_mean_kernel(const float* __restrict__ x,
                               const float* __restrict__ gam,
                               const float* __restrict__ bet,
                               float* __restrict__ out) {
    int warp = (blockIdx.x * blockDim.x + threadIdx.x) >> 5;
    int lane = threadIdx.x & 31;
    if (warp >= NG) return;
    float4 g0 = *(const float4*)(gam + lane*8);
    float4 g1 = *(const float4*)(gam + lane*8 + 4);
    float4 b0 = *(const float4*)(bet + lane*8);
    float4 b1 = *(const float4*)(bet + lane*8 + 4);
    float gs[8] = {g0.x,g0.y,g0.z,g0.w,g1.x,g1.y,g1.z,g1.w};
    float bs[8] = {b0.x,b0.y,b0.z,b0.w,b1.x,b1.y,b1.z,b1.w};
    float avg[8] = {0,0,0,0,0,0,0,0};
    #pragma unroll
    for (int s3 = 0; s3 < 3; s3++) {
        const float* row = x + ((size_t)warp*3 + s3) * Dn;
        float4 a0 = *(const float4*)(row + lane*8);
        float4 a1 = *(const float4*)(row + lane*8 + 4);
        float vals[8] = {a0.x,a0.y,a0.z,a0.w,a1.x,a1.y,a1.z,a1.w};
        float s = 0.f, sq = 0.f;
        #pragma unroll
        for (int i = 0; i < 8; i++) { s += vals[i]; sq += vals[i]*vals[i]; }
        #pragma unroll
        for (int o = 16; o > 0; o >>= 1) {
            s  += __shfl_xor_sync(0xffffffffu, s,  o);
            sq += __shfl_xor_sync(0xffffffffu, sq, o);
        }
        float mean = s * (1.0f/Dn);
        float var  = sq * (1.0f/Dn) - mean*mean;
        float rstd = rsqrtf(var + 1e-5f);
        #pragma unroll
        for (int i = 0; i < 8; i++)
            avg[i] += ((vals[i]-mean)*rstd*gs[i] + bs[i]) * (1.0f/3.0f);
    }
    float* orow = out + (size_t)warp * Dn;
    *(float4*)(orow + lane*8)     = make_float4(avg[0],avg[1],avg[2],avg[3]);
    *(float4*)(orow + lane*8 + 4) = make_float4(avg[4],avg[5],avg[6],avg[7]);
}

// ---------------- host ----------------
extern "C" void kernel_launch(void* const* d_in, const int* in_sizes, int n_in,
                              void* d_out, int out_size) {
    const float* term  = (const float*)d_in[0];
    const float* pred  = (const float*)d_in[1];
    const float* Wq    = (const float*)d_in[2];
    const float* Wk    = (const float*)d_in[3];
    const float* Wv    = (const float*)d_in[4];
    const float* Wo    = (const float*)d_in[5];
    const float* bq    = (const float*)d_in[6];
    const float* bk    = (const float*)d_in[7];
    const float* bv    = (const float*)d_in[8];
    const float* bo    = (const float*)d_in[9];
    const float* ln1g  = (const float*)d_in[10];
    const float* ln1b  = (const float*)d_in[11];
    const float* ln2g  = (const float*)d_in[12];
    const float* ln2b  = (const float*)d_in[13];
    const float* W1    = (const float*)d_in[14];
    const float* b1    = (const float*)d_in[15];
    const float* W2    = (const float*)d_in[16];
    const float* b2    = (const float*)d_in[17];
    const float* lnfg  = (const float*)d_in[18];
    const float* lnfb  = (const float*)d_in[19];
    float* out = (float*)d_out;

    float *x, *bqkv;
    bf16 *h, *qkv, *o, *f, *wt;
    cudaGetSymbolAddress((void**)&x,   g_x);
    cudaGetSymbolAddress((void**)&h,   g_h);
    cudaGetSymbolAddress((void**)&qkv, g_qkv);
    cudaGetSymbolAddress((void**)&o,   g_o);
    cudaGetSymbolAddress((void**)&f,   g_f);
    cudaGetSymbolAddress((void**)&wt,  g_wt);
    cudaGetSymbolAddress((void**)&bqkv,g_bqkv);

    cudaFuncSetAttribute(gemm_tc<0,false,true >, cudaFuncAttributeMaxDynamicSharedMemorySize, GEMM_SMEM_BYTES);
    cudaFuncSetAttribute(gemm_tc<0,true ,false>, cudaFuncAttributeMaxDynamicSharedMemorySize, GEMM_SMEM_BYTES);
    cudaFuncSetAttribute(gemm_tc<1,false,true >, cudaFuncAttributeMaxDynamicSharedMemorySize, GEMM_SMEM_BYTES);

    // weight prep (both layers, one launch each) + build x
    transpose_all<<<2*768, dim3(32,8)>>>(Wq, Wk, Wv, Wo, W1, W2, wt);
    concat_bias_kernel<<<6, 256>>>(bq, bk, bv, bqkv);
    {
        int nv = MROWS * (Dn/4);
        build_x_kernel<<<(nv + 255)/256, 256>>>(term, pred, x);
    }

    for (int l = 0; l < NLn; l++) {
        const bf16* wl = wt + (size_t)l*WT_LAYER;

        // LN1 -> h (bf16)
        ln_kernel<<<MROWS/8, 256>>>(x, ln1g + l*Dn, ln1b + l*Dn, h);

        // fused QKV GEMM: [MROWS,256] @ [256,768] -> qkv bf16
        gemm_tc<0,false,true><<<dim3(6, MROWS/128), 128, GEMM_SMEM_BYTES>>>(
            h, Dn, wl, bqkv + l*3*Dn, nullptr, qkv, 3*Dn, Dn);

        // attention
        attn_kernel<<<NG*Hn/8, 256>>>(qkv, o);

        // output projection + residual -> x fp32
        gemm_tc<0,true,false><<<dim3(2, MROWS/128), 128, GEMM_SMEM_BYTES>>>(
            o, Dn, wl + 196608, bo + l*Dn, x, x, Dn, Dn);

        // LN2 -> h
        ln_kernel<<<MROWS/8, 256>>>(x, ln2g + l*Dn, ln2b + l*Dn, h);

        // FFN up (relu) -> f bf16
        gemm_tc<1,false,true><<<dim3(8, MROWS/128), 128, GEMM_SMEM_BYTES>>>(
            h, Dn, wl + 262144, b1 + l*FFn, nullptr, f, FFn, Dn);

        // FFN down + residual -> x fp32
        gemm_tc<0,true,false><<<dim3(2, MROWS/128), 128, GEMM_SMEM_BYTES>>>(
            f, FFn, wl + 524288, b2 + l*Dn, x, x, Dn, FFn);
    }

    // fused final LN + mean pool
    ln_mean_kernel<<<NG/8, 256>>>(x, lnfg, lnfb, out);
    (void)in_sizes; (void)n_in; (void)out_size;
}